// round 13
// baseline (speedup 1.0000x reference)
#include <cuda_runtime.h>
#include <stdint.h>
#include <math.h>

// 1/sqrt(1 + 1e-3)
#define ISRC 0.9995003746877732f
#define XS 68                      // x row stride (floats)
#define KEXP -14.42695040888963f   // -10 * log2(e)
#define KINV (1.0f / KEXP)

typedef unsigned long long ull;

// scratch (static __device__ arrays: allocation-free)
__device__ float g_x0[64 * 32768];       // GNN output, (B, N*64) row-major
__device__ float g_part[256 * 64 * 128]; // split-K partials: (kchunk, b, d)

// ---------------- f32x2 helpers (Blackwell packed fp32) ----------------
__device__ __forceinline__ ull pk2(float a, float b) {
    ull r; asm("mov.b64 %0,{%1,%2};" : "=l"(r) : "f"(a), "f"(b)); return r;
}
__device__ __forceinline__ void up2(ull p, float& a, float& b) {
    asm("mov.b64 {%0,%1},%2;" : "=f"(a), "=f"(b) : "l"(p));
}
__device__ __forceinline__ ull add2(ull a, ull b) {
    ull r; asm("add.rn.f32x2 %0,%1,%2;" : "=l"(r) : "l"(a), "l"(b)); return r;
}
__device__ __forceinline__ ull fma2_(ull a, ull b, ull c) {
    ull r; asm("fma.rn.f32x2 %0,%1,%2,%3;" : "=l"(r) : "l"(a), "l"(b), "l"(c));
    return r;
}

// ---------------- fast math ----------------
__device__ __forceinline__ float ex2f(float x) {
    float r; asm("ex2.approx.ftz.f32 %0,%1;" : "=f"(r) : "f"(x)); return r;
}
__device__ __forceinline__ float rcpf(float x) {
    float r; asm("rcp.approx.ftz.f32 %0,%1;" : "=f"(r) : "f"(x)); return r;
}
// tanh(y) = 1 - 2/(exp(2y)+1), branchless, saturates correctly
__device__ __forceinline__ float ftanh(float y) {
    float e = ex2f(y * 2.885390081777927f);   // 2*log2(e)
    return fmaf(-2.0f, rcpf(e + 1.0f), 1.0f);
}

// ---------------- cluster / DSMEM helpers ----------------
__device__ __forceinline__ uint32_t smem_u32(const void* p) {
    uint32_t a;
    asm("{ .reg .u64 t; cvta.to.shared.u64 t, %1; cvt.u32.u64 %0, t; }"
        : "=r"(a) : "l"(p));
    return a;
}
__device__ __forceinline__ void cluster_sync_() {
    asm volatile("barrier.cluster.arrive.aligned;" ::: "memory");
    asm volatile("barrier.cluster.wait.aligned;" ::: "memory");
}
__device__ __forceinline__ uint32_t mapa_(uint32_t local, uint32_t rank) {
    uint32_t r;
    asm("mapa.shared::cluster.u32 %0, %1, %2;" : "=r"(r) : "r"(local), "r"(rank));
    return r;
}
__device__ __forceinline__ void st_cluster_f32(uint32_t addr, float v) {
    asm volatile("st.shared::cluster.f32 [%0],%1;" :: "r"(addr), "f"(v) : "memory");
}

// ---------------- pairwise S/T' via norm expansion ----------------
// c block layout: [x | y | z | w | n] each 512 floats; n = KEXP * |c|^2.
// t_ij = KEXP*d_ij = n_j + KEXP*n_i_raw + sum_m c_j,m * (-2*KEXP*c_i,m)
// w = ex2(t);  S += w;  T' += t*w  (T = T'/KEXP recovered in epilogue)
template <int ND>
__device__ __forceinline__ void pairwise2(
    const float* __restrict__ cb, float* sp, float* tp, int tid, int h)
{
    const int i  = tid & 255;
    const int jh = tid >> 8;
    const int gi = h * 256 + i;
    const float* cx = cb;
    const float* cy = cb + 512;
    const float* cz = cb + 1024;
    const float* cw = cb + 1536;
    const float* cn = cb + 2048;

    const float cix = cx[gi], ciy = cy[gi];
    float nrm = cix * cix + ciy * ciy;
    float ciz = 0.f, ciw = 0.f;
    if (ND == 4) { ciz = cz[gi]; ciw = cw[gi]; nrm += ciz * ciz + ciw * ciw; }
    const float TK = -2.0f * KEXP;
    const ull gx = pk2(TK * cix, TK * cix);
    const ull gy = pk2(TK * ciy, TK * ciy);
    ull gz = 0ull, gw = 0ull;
    if (ND == 4) { gz = pk2(TK * ciz, TK * ciz); gw = pk2(TK * ciw, TK * ciw); }
    const float knif = KEXP * nrm;
    const ull kni = pk2(knif, knif);

    ull Sa = 0ull, Ta = 0ull, Sb = 0ull, Tb = 0ull;
    const int j0 = jh * 256;
#pragma unroll 4
    for (int j = j0; j < j0 + 256; j += 4) {
        ulonglong2 N = *reinterpret_cast<const ulonglong2*>(cn + j);
        ulonglong2 X = *reinterpret_cast<const ulonglong2*>(cx + j);
        ulonglong2 Y = *reinterpret_cast<const ulonglong2*>(cy + j);
        ull ta = add2(N.x, kni);
        ull tb = add2(N.y, kni);
        ta = fma2_(X.x, gx, ta);  tb = fma2_(X.y, gx, tb);
        ta = fma2_(Y.x, gy, ta);  tb = fma2_(Y.y, gy, tb);
        if (ND == 4) {
            ulonglong2 Z = *reinterpret_cast<const ulonglong2*>(cz + j);
            ulonglong2 W = *reinterpret_cast<const ulonglong2*>(cw + j);
            ta = fma2_(Z.x, gz, ta);  tb = fma2_(Z.y, gz, tb);
            ta = fma2_(W.x, gw, ta);  tb = fma2_(W.y, gw, tb);
        }
        float t0, t1, t2, t3; up2(ta, t0, t1); up2(tb, t2, t3);
        ull wa = pk2(ex2f(t0), ex2f(t1));
        ull wb = pk2(ex2f(t2), ex2f(t3));
        Sa = add2(Sa, wa); Ta = fma2_(ta, wa, Ta);
        Sb = add2(Sb, wb); Tb = fma2_(tb, wb, Tb);
    }
    ull S2 = add2(Sa, Sb), T2 = add2(Ta, Tb);
    float s0, s1, u0, u1; up2(S2, s0, s1); up2(T2, u0, u1);
    sp[tid] = s0 + s1; tp[tid] = u0 + u1;
}

// ---------------- GEMM + epilogue (s/t read directly from sp/tp) -----------
template <int FP>
__device__ __forceinline__ void gemm_epi2(
    const float* x_s, const float* A_s, const float* sp, const float* tp,
    const float* m_s, const float* cn, int tid, float o[4][8])
{
    const int cs0 = (tid & 7) * 8;
    const int r0  = (tid >> 3) * 4;
    ull u[4][4], v[4][4];
#pragma unroll
    for (int r = 0; r < 4; r++)
#pragma unroll
        for (int c = 0; c < 4; c++) { u[r][c] = 0ull; v[r][c] = 0ull; }

    const float* xb = x_s + r0 * XS;
#pragma unroll 2
    for (int kq = 0; kq < FP / 4; kq++) {
        float xq[4][4];
#pragma unroll
        for (int r = 0; r < 4; r++)
            *reinterpret_cast<float4*>(xq[r]) =
                *reinterpret_cast<const float4*>(xb + r * XS + kq * 4);
#pragma unroll
        for (int j = 0; j < 4; j++) {
            const int k = kq * 4 + j;
            ulonglong2 a01 = *reinterpret_cast<const ulonglong2*>(&A_s[k * 64 + cs0]);
            ulonglong2 a23 = *reinterpret_cast<const ulonglong2*>(&A_s[k * 64 + cs0 + 4]);
            ulonglong2 q01 = *reinterpret_cast<const ulonglong2*>(&A_s[(FP + k) * 64 + cs0]);
            ulonglong2 q23 = *reinterpret_cast<const ulonglong2*>(&A_s[(FP + k) * 64 + cs0 + 4]);
#pragma unroll
            for (int r = 0; r < 4; r++) {
                ull xp = pk2(xq[r][j], xq[r][j]);
                u[r][0] = fma2_(xp, a01.x, u[r][0]);
                u[r][1] = fma2_(xp, a01.y, u[r][1]);
                u[r][2] = fma2_(xp, a23.x, u[r][2]);
                u[r][3] = fma2_(xp, a23.y, u[r][3]);
                v[r][0] = fma2_(xp, q01.x, v[r][0]);
                v[r][1] = fma2_(xp, q01.y, v[r][1]);
                v[r][2] = fma2_(xp, q23.x, v[r][2]);
                v[r][3] = fma2_(xp, q23.y, v[r][3]);
            }
        }
    }
#pragma unroll
    for (int r = 0; r < 4; r++) {
        const int i = r0 + r;
        const float m = m_s[i];
        const float s = fmaf(m, sp[i] + sp[i + 256], -1.f);
        const float t = (tp[i] + tp[i + 256]) * (m * KINV);
        const ull s2 = pk2(s, s);
#pragma unroll
        for (int c2 = 0; c2 < 4; c2++) {
            ull y2 = fma2_(s2, v[r][c2], u[r][c2]);
            float yl, yh; up2(y2, yl, yh);
            const int c = cs0 + c2 * 2;
            float a0 = (fmaf(t, A_s[2 * FP * 64 + c],     yl) + cn[c])     * m;
            float a1 = (fmaf(t, A_s[2 * FP * 64 + c + 1], yh) + cn[c + 1]) * m;
            o[r][c2 * 2]     = ftanh(fmaf(cn[64 + c],     a0, cn[128 + c]));
            o[r][c2 * 2 + 1] = ftanh(fmaf(cn[64 + c + 1], a1, cn[128 + c + 1]));
        }
    }
}

// ----------------------------------------------------------------------------
// Fused GNN, cluster of 2 CTAs per batch. Double-buffered A (prefetch hidden
// under pairwise), c+norm pushed from epilogue registers local + peer DSMEM.
// Per layer: 2 syncthreads + 1 cluster_sync.
// ----------------------------------------------------------------------------
__global__ __launch_bounds__(512, 1) __cluster_dims__(2, 1, 1)
void gnn_fused_kernel(
    const float* __restrict__ xx,
    const float* __restrict__ e1, const float* __restrict__ e2,
    const float* __restrict__ e3,
    const float* __restrict__ A0, const float* __restrict__ b0,
    const float* __restrict__ Ar, const float* __restrict__ br,
    const float* __restrict__ bng, const float* __restrict__ bnb)
{
    extern __shared__ float sm[];
    float* cbuf   = sm;                   // 2 blocks x 5 arrays x 512 = 5120
    float* x_s    = cbuf + 5120;          // 256*XS = 17408
    float* A_s    = x_s + 256 * XS;       // 2 x 8256 = 16512
    float* m_s    = A_s + 16512;          // 256
    float* sp     = m_s + 256;            // 512
    float* tp     = sp + 512;             // 512
    float* cn_all = tp + 512;             // 5*192 = 960

    const int h   = blockIdx.x;           // rank in cluster (row half)
    const int ph  = 1 - h;
    const int b   = blockIdx.y;
    const int tid = threadIdx.x;
    const int cs0 = (tid & 7) * 8;
    const int r0  = (tid >> 3) * 4;
    const bool pusher = (cs0 == 56);      // owns output cols 56..63

    // ---- init: mask, layer-0 features (FP=36), c block0, A0 buf0, cn_all ---
    if (tid < 256) {
        const float* r = xx + ((size_t)b * 512 + h * 256 + tid) * 30;
        m_s[tid] = r[0];
        int i1 = (int)fabsf(r[27]);
        int i2 = (int)fabsf(r[28]);
        int i3 = (int)fabsf(r[29]);
        float* xr = x_s + tid * XS;
        xr[0] = e1[2 * i1]; xr[1] = e1[2 * i1 + 1];
        xr[2] = e2[2 * i2]; xr[3] = e2[2 * i2 + 1];
        xr[4] = e3[2 * i3]; xr[5] = e3[2 * i3 + 1];
#pragma unroll
        for (int k = 0; k < 27; k++) xr[6 + k] = r[k];
        xr[33] = 0.f; xr[34] = 0.f; xr[35] = 0.f;
    }
    {   // layer-0 c (ND=2) + norms for ALL 512 rows straight from xx
        const float* row = xx + ((size_t)b * 512 + tid) * 30;
        float vx = row[25], vy = row[26];
        cbuf[tid]        = vx;
        cbuf[512 + tid]  = vy;
        cbuf[2048 + tid] = KEXP * (vx * vx + vy * vy);
    }
    // stage A0 padded to FP=36 into A buffer 0
    for (int idx = tid; idx < 73 * 64; idx += 512) {
        int kp = idx >> 6, c = idx & 63;
        float val = 0.f;
        if (kp < 33)                  val = A0[kp * 64 + c];
        else if (kp >= 36 && kp < 69) val = A0[(kp - 3) * 64 + c];
        else if (kp == 72)            val = A0[66 * 64 + c];
        A_s[idx] = val;
    }
    // prestage all per-layer constants
    for (int idx = tid; idx < 960; idx += 512) {
        int l = idx / 192, r = idx - l * 192;
        float val;
        if (r < 64)        val = (l == 0) ? b0[r] : br[(l - 1) * 64 + r];
        else if (r < 128)  val = bng[l * 64 + (r - 64)] * ISRC;
        else               val = bnb[l * 64 + (r - 128)];
        cn_all[idx] = val;
    }
    __syncthreads();

    // ---- layers 0..4 ----
#pragma unroll 1
    for (int l = 0; l < 5; l++) {
        const float* Abuf = A_s + (l & 1) * 8256;
        float* Anext      = A_s + ((l + 1) & 1) * 8256;
        const float* cbR  = cbuf + (l & 1) * 2560;
        float* cbW        = cbuf + ((l + 1) & 1) * 2560;
        const float* cn   = cn_all + l * 192;

        // prefetch next layer's A (LDG now, STS after pairwise sync)
        float4 pf[5]; int npf = 0;
        if (l < 4) {
            const float* A = Ar + l * 8256;
            for (int idx = tid; idx < 2064; idx += 512)
                pf[npf++] = reinterpret_cast<const float4*>(A)[idx];
        }

        if (l == 0) pairwise2<2>(cbR, sp, tp, tid, h);
        else        pairwise2<4>(cbR, sp, tp, tid, h);
        __syncthreads();   // sp/tp visible; also orders prev writeback of x_s

        if (l < 4) {
            int n = 0;
            for (int idx = tid; idx < 2064; idx += 512)
                reinterpret_cast<float4*>(Anext)[idx] = pf[n++];
        }

        float o[4][8];
        if (l == 0) gemm_epi2<36>(x_s, Abuf, sp, tp, m_s, cn, tid, o);
        else        gemm_epi2<64>(x_s, Abuf, sp, tp, m_s, cn, tid, o);

        if (l < 4) {
            if (pusher) {
                uint32_t lb = smem_u32(cbW);
                uint32_t pb = mapa_(lb, (uint32_t)ph);
#pragma unroll
                for (int r = 0; r < 4; r++) {
                    int gi = h * 256 + r0 + r;
                    float vx = o[r][4], vy = o[r][5], vz = o[r][6], vw = o[r][7];
                    float nj = KEXP * (vx * vx + vy * vy + vz * vz + vw * vw);
                    cbW[gi]        = vx;  cbW[512 + gi]  = vy;
                    cbW[1024 + gi] = vz;  cbW[1536 + gi] = vw;
                    cbW[2048 + gi] = nj;
                    uint32_t off = (uint32_t)gi * 4u;
                    st_cluster_f32(pb + off,          vx);
                    st_cluster_f32(pb + 2048u + off,  vy);
                    st_cluster_f32(pb + 4096u + off,  vz);
                    st_cluster_f32(pb + 6144u + off,  vw);
                    st_cluster_f32(pb + 8192u + off,  nj);
                }
            }
            __syncthreads();   // all x_s reads of this layer done
#pragma unroll
            for (int r = 0; r < 4; r++) {
                float4* dst = reinterpret_cast<float4*>(x_s + (r0 + r) * XS + cs0);
                dst[0] = make_float4(o[r][0], o[r][1], o[r][2], o[r][3]);
                dst[1] = make_float4(o[r][4], o[r][5], o[r][6], o[r][7]);
            }
            cluster_sync_();   // c pushes (both CTAs) + writeback ordered
        } else {
            // last layer: write straight to global for the dense head
#pragma unroll
            for (int r = 0; r < 4; r++) {
                float4* dst = reinterpret_cast<float4*>(
                    g_x0 + (size_t)b * 32768 + (h * 256 + r0 + r) * 64 + cs0);
                dst[0] = make_float4(o[r][0], o[r][1], o[r][2], o[r][3]);
                dst[1] = make_float4(o[r][4], o[r][5], o[r][6], o[r][7]);
            }
        }
    }
}

// ----------------------------------------------------------------------------
// Dense layer 0 split-K: 256 CTAs, each owns a K-chunk of 128 (2 CTAs/SM).
// Deterministic: partials stored, reduced in finalize (no float atomics).
// ----------------------------------------------------------------------------
#define D0XS 129
__global__ __launch_bounds__(256, 2) void dense0_kernel(const float* __restrict__ W)
{
    extern __shared__ float sm[];
    float* Xs = sm;                 // 64 x 129 (padded)
    float* Ws = Xs + 64 * D0XS;     // 128 x 128
    const int tid = threadIdx.x;
    const int kc  = blockIdx.x;

    for (int idx = tid; idx < 64 * 128; idx += 256) {
        int bb = idx >> 7, k = idx & 127;
        Xs[bb * D0XS + k] = g_x0[(size_t)bb * 32768 + kc * 128 + k];
    }
    const float* wsrc = W + (size_t)kc * 128 * 128;
    for (int idx = tid; idx < 128 * 128 / 4; idx += 256)
        reinterpret_cast<float4*>(Ws)[idx] =
            reinterpret_cast<const float4*>(wsrc)[idx];
    __syncthreads();

    const int rg = tid >> 4;   // 0..15 -> rows rg*4..rg*4+3
    const int cg = tid & 15;   // 0..15 -> cols cg*8..cg*8+7
    ull acc[4][4];
#pragma unroll
    for (int r = 0; r < 4; r++)
#pragma unroll
        for (int c = 0; c < 4; c++) acc[r][c] = 0ull;

#pragma unroll 2
    for (int k = 0; k < 128; k++) {
        ulonglong2 w01 = *reinterpret_cast<const ulonglong2*>(&Ws[k * 128 + cg * 8]);
        ulonglong2 w23 = *reinterpret_cast<const ulonglong2*>(&Ws[k * 128 + cg * 8 + 4]);
#pragma unroll
        for (int r = 0; r < 4; r++) {
            float xv = Xs[(rg * 4 + r) * D0XS + k];
            ull xp = pk2(xv, xv);
            acc[r][0] = fma2_(xp, w01.x, acc[r][0]);
            acc[r][1] = fma2_(xp, w01.y, acc[r][1]);
            acc[r][2] = fma2_(xp, w23.x, acc[r][2]);
            acc[r][3] = fma2_(xp, w23.y, acc[r][3]);
        }
    }
    float* dst = g_part + (size_t)kc * 8192;
#pragma unroll
    for (int r = 0; r < 4; r++) {
        ulonglong2* d = reinterpret_cast<ulonglong2*>(&dst[(rg * 4 + r) * 128 + cg * 8]);
        d[0] = make_ulonglong2(acc[r][0], acc[r][1]);
        d[1] = make_ulonglong2(acc[r][2], acc[r][3]);
    }
}

// ----------------------------------------------------------------------------
// Finalize: reduce partials, BN+sigmoid, dense1, BN+sigmoid, W2, write (64,4)
// ----------------------------------------------------------------------------
__global__ __launch_bounds__(128, 1) void finalize_kernel(
    const float* __restrict__ db0, const float* __restrict__ dW1,
    const float* __restrict__ db1, const float* __restrict__ dbng,
    const float* __restrict__ dbnb, const float* __restrict__ W2,
    const float* __restrict__ b2, float* __restrict__ out)
{
    __shared__ float h0[128];
    __shared__ float h1[128];
    const int b = blockIdx.x;
    const int d = threadIdx.x;

    float a = db0[d];
#pragma unroll 4
    for (int kc = 0; kc < 256; kc++) a += g_part[(size_t)kc * 8192 + b * 128 + d];
    a = fmaf(dbng[d] * ISRC, a, dbnb[d]);
    h0[d] = 1.f / (1.f + __expf(-a));
    __syncthreads();

    float s = 0.f;
#pragma unroll 8
    for (int k = 0; k < 128; k++) s = fmaf(h0[k], dW1[k * 128 + d], s);
    s += db1[d];
    s = fmaf(dbng[128 + d] * ISRC, s, dbnb[128 + d]);
    h1[d] = 1.f / (1.f + __expf(-s));
    __syncthreads();

    if (d < 4) {
        float o = 0.f;
        if (d < 2) {
            o = b2[d];
            for (int k = 0; k < 128; k++) o = fmaf(h1[k], W2[k * 2 + d], o);
        }
        out[b * 4 + d] = o;
    }
}

// ----------------------------------------------------------------------------
extern "C" void kernel_launch(void* const* d_in, const int* in_sizes, int n_in,
                              void* d_out, int out_size)
{
    const float* xx   = (const float*)d_in[0];
    const float* emb1 = (const float*)d_in[1];
    const float* emb2 = (const float*)d_in[2];
    const float* emb3 = (const float*)d_in[3];
    const float* A0   = (const float*)d_in[4];
    const float* b0   = (const float*)d_in[5];
    const float* Ar   = (const float*)d_in[6];
    const float* br   = (const float*)d_in[7];
    const float* bng  = (const float*)d_in[8];
    const float* bnb  = (const float*)d_in[9];
    const float* dW0  = (const float*)d_in[10];
    const float* db0  = (const float*)d_in[11];
    const float* dW1  = (const float*)d_in[12];
    const float* db1  = (const float*)d_in[13];
    const float* dbng = (const float*)d_in[14];
    const float* dbnb = (const float*)d_in[15];
    const float* W2   = (const float*)d_in[16];
    const float* b2   = (const float*)d_in[17];
    float* out = (float*)d_out;

    // 5120 + 17408 + 16512 + 256 + 512 + 512 + 960 = 41280 floats
    const int G_SMEM  = 41280 * 4;
    const int D0_SMEM = (64 * D0XS + 128 * 128) * 4;

    cudaFuncSetAttribute(gnn_fused_kernel,
                         cudaFuncAttributeMaxDynamicSharedMemorySize, G_SMEM);
    cudaFuncSetAttribute(dense0_kernel,
                         cudaFuncAttributeMaxDynamicSharedMemorySize, D0_SMEM);

    dim3 grid(2, 64);
    gnn_fused_kernel<<<grid, 512, G_SMEM>>>(
        xx, emb1, emb2, emb3, A0, b0, Ar, br, bng, bnb);
    dense0_kernel<<<256, 256, D0_SMEM>>>(dW0);
    finalize_kernel<<<64, 128>>>(db0, dW1, db1, dbng, dbnb, W2, b2, out);
}

// round 16
// speedup vs baseline: 1.0359x; 1.0359x over previous
#include <cuda_runtime.h>
#include <stdint.h>
#include <math.h>

// 1/sqrt(1 + 1e-3)
#define ISRC 0.9995003746877732f
#define XS 68                      // x row stride (floats)
#define KEXP -14.42695040888963f   // -10 * log2(e)
#define KINV (1.0f / KEXP)

typedef unsigned long long ull;

// scratch (static __device__ arrays: allocation-free)
__device__ float g_x0[64 * 32768];       // GNN output, (B, N*64) row-major
__device__ float g_part[128 * 64 * 128]; // split-K partials: (kchunk, b, d)

// ---------------- f32x2 helpers (Blackwell packed fp32) ----------------
__device__ __forceinline__ ull pk2(float a, float b) {
    ull r; asm("mov.b64 %0,{%1,%2};" : "=l"(r) : "f"(a), "f"(b)); return r;
}
__device__ __forceinline__ void up2(ull p, float& a, float& b) {
    asm("mov.b64 {%0,%1},%2;" : "=f"(a), "=f"(b) : "l"(p));
}
__device__ __forceinline__ ull add2(ull a, ull b) {
    ull r; asm("add.rn.f32x2 %0,%1,%2;" : "=l"(r) : "l"(a), "l"(b)); return r;
}
__device__ __forceinline__ ull fma2_(ull a, ull b, ull c) {
    ull r; asm("fma.rn.f32x2 %0,%1,%2,%3;" : "=l"(r) : "l"(a), "l"(b), "l"(c));
    return r;
}

// ---------------- fast math ----------------
__device__ __forceinline__ float ex2f(float x) {
    float r; asm("ex2.approx.ftz.f32 %0,%1;" : "=f"(r) : "f"(x)); return r;
}
__device__ __forceinline__ float rcpf(float x) {
    float r; asm("rcp.approx.ftz.f32 %0,%1;" : "=f"(r) : "f"(x)); return r;
}
// tanh(y) = 1 - 2/(exp(2y)+1), branchless, saturates correctly
__device__ __forceinline__ float ftanh(float y) {
    float e = ex2f(y * 2.885390081777927f);   // 2*log2(e)
    return fmaf(-2.0f, rcpf(e + 1.0f), 1.0f);
}

// ---------------- cluster / DSMEM helpers ----------------
__device__ __forceinline__ uint32_t smem_u32(const void* p) {
    uint32_t a;
    asm("{ .reg .u64 t; cvta.to.shared.u64 t, %1; cvt.u32.u64 %0, t; }"
        : "=r"(a) : "l"(p));
    return a;
}
__device__ __forceinline__ void cluster_sync_() {
    asm volatile("barrier.cluster.arrive.aligned;" ::: "memory");
    asm volatile("barrier.cluster.wait.aligned;" ::: "memory");
}
__device__ __forceinline__ uint32_t mapa_(uint32_t local, uint32_t rank) {
    uint32_t r;
    asm("mapa.shared::cluster.u32 %0, %1, %2;" : "=r"(r) : "r"(local), "r"(rank));
    return r;
}
__device__ __forceinline__ void st_cluster_f32(uint32_t addr, float v) {
    asm volatile("st.shared::cluster.f32 [%0],%1;" :: "r"(addr), "f"(v) : "memory");
}

// ---------------- pairwise S/T' via norm expansion ----------------
// c block layout: [x | y | z | w | n] each 512 floats; n = KEXP * |c|^2.
// t_ij = KEXP*d_ij = n_j + KEXP*n_i + sum_m c_j,m * (-2*KEXP*c_i,m)
// w = ex2(t);  S += w;  T' += t*w  (T = T'/KEXP recovered in epilogue)
template <int ND>
__device__ __forceinline__ void pairwise2(
    const float* __restrict__ cb, float* sp, float* tp, int tid, int h)
{
    const int i  = tid & 255;
    const int jh = tid >> 8;
    const int gi = h * 256 + i;
    const float* cx = cb;
    const float* cy = cb + 512;
    const float* cz = cb + 1024;
    const float* cw = cb + 1536;
    const float* cn = cb + 2048;

    const float cix = cx[gi], ciy = cy[gi];
    float nrm = cix * cix + ciy * ciy;
    float ciz = 0.f, ciw = 0.f;
    if (ND == 4) { ciz = cz[gi]; ciw = cw[gi]; nrm += ciz * ciz + ciw * ciw; }
    const float TK = -2.0f * KEXP;
    const ull gx = pk2(TK * cix, TK * cix);
    const ull gy = pk2(TK * ciy, TK * ciy);
    ull gz = 0ull, gw = 0ull;
    if (ND == 4) { gz = pk2(TK * ciz, TK * ciz); gw = pk2(TK * ciw, TK * ciw); }
    const float knif = KEXP * nrm;
    const ull kni = pk2(knif, knif);

    ull Sa = 0ull, Ta = 0ull, Sb = 0ull, Tb = 0ull;
    const int j0 = jh * 256;
#pragma unroll 4
    for (int j = j0; j < j0 + 256; j += 4) {
        ulonglong2 N = *reinterpret_cast<const ulonglong2*>(cn + j);
        ulonglong2 X = *reinterpret_cast<const ulonglong2*>(cx + j);
        ulonglong2 Y = *reinterpret_cast<const ulonglong2*>(cy + j);
        ull ta = add2(N.x, kni);
        ull tb = add2(N.y, kni);
        ta = fma2_(X.x, gx, ta);  tb = fma2_(X.y, gx, tb);
        ta = fma2_(Y.x, gy, ta);  tb = fma2_(Y.y, gy, tb);
        if (ND == 4) {
            ulonglong2 Z = *reinterpret_cast<const ulonglong2*>(cz + j);
            ulonglong2 W = *reinterpret_cast<const ulonglong2*>(cw + j);
            ta = fma2_(Z.x, gz, ta);  tb = fma2_(Z.y, gz, tb);
            ta = fma2_(W.x, gw, ta);  tb = fma2_(W.y, gw, tb);
        }
        float t0, t1, t2, t3; up2(ta, t0, t1); up2(tb, t2, t3);
        ull wa = pk2(ex2f(t0), ex2f(t1));
        ull wb = pk2(ex2f(t2), ex2f(t3));
        Sa = add2(Sa, wa); Ta = fma2_(ta, wa, Ta);
        Sb = add2(Sb, wb); Tb = fma2_(tb, wb, Tb);
    }
    ull S2 = add2(Sa, Sb), T2 = add2(Ta, Tb);
    float s0, s1, u0, u1; up2(S2, s0, s1); up2(T2, u0, u1);
    sp[tid] = s0 + s1; tp[tid] = u0 + u1;
}

// ---------------- GEMM accumulation only (no epilogue) ---------------------
template <int FP>
__device__ __forceinline__ void gemm_accum(
    const float* x_s, const float* A_s, int tid, ull u[4][4], ull v[4][4])
{
    const int cs0 = (tid & 7) * 8;
    const int r0  = (tid >> 3) * 4;
#pragma unroll
    for (int r = 0; r < 4; r++)
#pragma unroll
        for (int c = 0; c < 4; c++) { u[r][c] = 0ull; v[r][c] = 0ull; }

    const float* xb = x_s + r0 * XS;
#pragma unroll 2
    for (int kq = 0; kq < FP / 4; kq++) {
        float xq[4][4];
#pragma unroll
        for (int r = 0; r < 4; r++)
            *reinterpret_cast<float4*>(xq[r]) =
                *reinterpret_cast<const float4*>(xb + r * XS + kq * 4);
#pragma unroll
        for (int j = 0; j < 4; j++) {
            const int k = kq * 4 + j;
            ulonglong2 a01 = *reinterpret_cast<const ulonglong2*>(&A_s[k * 64 + cs0]);
            ulonglong2 a23 = *reinterpret_cast<const ulonglong2*>(&A_s[k * 64 + cs0 + 4]);
            ulonglong2 q01 = *reinterpret_cast<const ulonglong2*>(&A_s[(FP + k) * 64 + cs0]);
            ulonglong2 q23 = *reinterpret_cast<const ulonglong2*>(&A_s[(FP + k) * 64 + cs0 + 4]);
#pragma unroll
            for (int r = 0; r < 4; r++) {
                ull xp = pk2(xq[r][j], xq[r][j]);
                u[r][0] = fma2_(xp, a01.x, u[r][0]);
                u[r][1] = fma2_(xp, a01.y, u[r][1]);
                u[r][2] = fma2_(xp, a23.x, u[r][2]);
                u[r][3] = fma2_(xp, a23.y, u[r][3]);
                v[r][0] = fma2_(xp, q01.x, v[r][0]);
                v[r][1] = fma2_(xp, q01.y, v[r][1]);
                v[r][2] = fma2_(xp, q23.x, v[r][2]);
                v[r][3] = fma2_(xp, q23.y, v[r][3]);
            }
        }
    }
}

// ---------------- epilogue: combine u/v with s,t; bias/mask/BN/tanh --------
template <int FP>
__device__ __forceinline__ void epilogue(
    const float* A_s, const float* sp, const float* tp,
    const float* m_s, const float* cn, int tid,
    ull u[4][4], ull v[4][4], float o[4][8])
{
    const int cs0 = (tid & 7) * 8;
    const int r0  = (tid >> 3) * 4;
#pragma unroll
    for (int r = 0; r < 4; r++) {
        const int i = r0 + r;
        const float m = m_s[i];
        const float s = fmaf(m, sp[i] + sp[i + 256], -1.f);
        const float t = (tp[i] + tp[i + 256]) * (m * KINV);
        const ull s2 = pk2(s, s);
#pragma unroll
        for (int c2 = 0; c2 < 4; c2++) {
            ull y2 = fma2_(s2, v[r][c2], u[r][c2]);
            float yl, yh; up2(y2, yl, yh);
            const int c = cs0 + c2 * 2;
            float a0 = (fmaf(t, A_s[2 * FP * 64 + c],     yl) + cn[c])     * m;
            float a1 = (fmaf(t, A_s[2 * FP * 64 + c + 1], yh) + cn[c + 1]) * m;
            o[r][c2 * 2]     = ftanh(fmaf(cn[64 + c],     a0, cn[128 + c]));
            o[r][c2 * 2 + 1] = ftanh(fmaf(cn[64 + c + 1], a1, cn[128 + c + 1]));
        }
    }
}

// ----------------------------------------------------------------------------
// Fused GNN, cluster of 2 CTAs per batch. Per-layer barrier structure:
//   pairwise -> STS(A prefetch) -> GEMM-accum -> ONE syncthreads ->
//   epilogue (+c push local & peer) -> x writeback -> ONE cluster_sync
// The long barrier-free pairwise+GEMM region lets warps desync so MUFU/LDS
// of laggards overlap FFMA2 of leaders.
// ----------------------------------------------------------------------------
__global__ __launch_bounds__(512, 1) __cluster_dims__(2, 1, 1)
void gnn_fused_kernel(
    const float* __restrict__ xx,
    const float* __restrict__ e1, const float* __restrict__ e2,
    const float* __restrict__ e3,
    const float* __restrict__ A0, const float* __restrict__ b0,
    const float* __restrict__ Ar, const float* __restrict__ br,
    const float* __restrict__ bng, const float* __restrict__ bnb)
{
    extern __shared__ float sm[];
    float* cbuf   = sm;                   // 2 blocks x 5 arrays x 512 = 5120
    float* x_s    = cbuf + 5120;          // 256*XS = 17408
    float* A_s    = x_s + 256 * XS;       // 2 x 8256 = 16512
    float* m_s    = A_s + 16512;          // 256
    float* sp     = m_s + 256;            // 512
    float* tp     = sp + 512;             // 512
    float* cn_all = tp + 512;             // 5*192 = 960

    const int h   = blockIdx.x;           // rank in cluster (row half)
    const int ph  = 1 - h;
    const int b   = blockIdx.y;
    const int tid = threadIdx.x;
    const int cs0 = (tid & 7) * 8;
    const int r0  = (tid >> 3) * 4;
    const bool pusher = (cs0 == 56);      // owns output cols 56..63

    // ---- init: mask, layer-0 features (FP=36), c block0, A0 buf0, cn_all ---
    if (tid < 256) {
        const float* r = xx + ((size_t)b * 512 + h * 256 + tid) * 30;
        m_s[tid] = r[0];
        int i1 = (int)fabsf(r[27]);
        int i2 = (int)fabsf(r[28]);
        int i3 = (int)fabsf(r[29]);
        float* xr = x_s + tid * XS;
        xr[0] = e1[2 * i1]; xr[1] = e1[2 * i1 + 1];
        xr[2] = e2[2 * i2]; xr[3] = e2[2 * i2 + 1];
        xr[4] = e3[2 * i3]; xr[5] = e3[2 * i3 + 1];
#pragma unroll
        for (int k = 0; k < 27; k++) xr[6 + k] = r[k];
        xr[33] = 0.f; xr[34] = 0.f; xr[35] = 0.f;
    }
    {   // layer-0 c (ND=2) + norms for ALL 512 rows straight from xx
        const float* row = xx + ((size_t)b * 512 + tid) * 30;
        float vx = row[25], vy = row[26];
        cbuf[tid]        = vx;
        cbuf[512 + tid]  = vy;
        cbuf[2048 + tid] = KEXP * (vx * vx + vy * vy);
    }
    // stage A0 padded to FP=36 into A buffer 0
    for (int idx = tid; idx < 73 * 64; idx += 512) {
        int kp = idx >> 6, c = idx & 63;
        float val = 0.f;
        if (kp < 33)                  val = A0[kp * 64 + c];
        else if (kp >= 36 && kp < 69) val = A0[(kp - 3) * 64 + c];
        else if (kp == 72)            val = A0[66 * 64 + c];
        A_s[idx] = val;
    }
    // prestage all per-layer constants
    for (int idx = tid; idx < 960; idx += 512) {
        int l = idx / 192, r = idx - l * 192;
        float val;
        if (r < 64)        val = (l == 0) ? b0[r] : br[(l - 1) * 64 + r];
        else if (r < 128)  val = bng[l * 64 + (r - 64)] * ISRC;
        else               val = bnb[l * 64 + (r - 128)];
        cn_all[idx] = val;
    }
    __syncthreads();

    // ---- layers 0..4 ----
#pragma unroll 1
    for (int l = 0; l < 5; l++) {
        const float* Abuf = A_s + (l & 1) * 8256;
        float* Anext      = A_s + ((l + 1) & 1) * 8256;
        const float* cbR  = cbuf + (l & 1) * 2560;
        float* cbW        = cbuf + ((l + 1) & 1) * 2560;
        const float* cn   = cn_all + l * 192;

        // prefetch next layer's A (LDG now; STS after pairwise, before GEMM —
        // Anext's last readers finished before the previous layer's barrier)
        float4 pf[5]; int npf = 0;
        if (l < 4) {
            const float* A = Ar + l * 8256;
            for (int idx = tid; idx < 2064; idx += 512)
                pf[npf++] = reinterpret_cast<const float4*>(A)[idx];
        }

        if (l == 0) pairwise2<2>(cbR, sp, tp, tid, h);
        else        pairwise2<4>(cbR, sp, tp, tid, h);

        if (l < 4) {
            int n = 0;
            for (int idx = tid; idx < 2064; idx += 512)
                reinterpret_cast<float4*>(Anext)[idx] = pf[n++];
        }

        ull u[4][4], v[4][4];
        if (l == 0) gemm_accum<36>(x_s, Abuf, tid, u, v);
        else        gemm_accum<64>(x_s, Abuf, tid, u, v);

        __syncthreads();   // sp/tp visible; all x_s & Abuf reads of layer done

        float o[4][8];
        if (l == 0) epilogue<36>(Abuf, sp, tp, m_s, cn, tid, u, v, o);
        else        epilogue<64>(Abuf, sp, tp, m_s, cn, tid, u, v, o);

        if (l < 4) {
            if (pusher) {
                uint32_t lb = smem_u32(cbW);
                uint32_t pb = mapa_(lb, (uint32_t)ph);
#pragma unroll
                for (int r = 0; r < 4; r++) {
                    int gi = h * 256 + r0 + r;
                    float vx = o[r][4], vy = o[r][5], vz = o[r][6], vw = o[r][7];
                    float nj = KEXP * (vx * vx + vy * vy + vz * vz + vw * vw);
                    cbW[gi]        = vx;  cbW[512 + gi]  = vy;
                    cbW[1024 + gi] = vz;  cbW[1536 + gi] = vw;
                    cbW[2048 + gi] = nj;
                    uint32_t off = (uint32_t)gi * 4u;
                    st_cluster_f32(pb + off,          vx);
                    st_cluster_f32(pb + 2048u + off,  vy);
                    st_cluster_f32(pb + 4096u + off,  vz);
                    st_cluster_f32(pb + 6144u + off,  vw);
                    st_cluster_f32(pb + 8192u + off,  nj);
                }
            }
            // writeback x (own rows; all reads of x_s completed at the sync)
#pragma unroll
            for (int r = 0; r < 4; r++) {
                float4* dst = reinterpret_cast<float4*>(x_s + (r0 + r) * XS + cs0);
                dst[0] = make_float4(o[r][0], o[r][1], o[r][2], o[r][3]);
                dst[1] = make_float4(o[r][4], o[r][5], o[r][6], o[r][7]);
            }
            cluster_sync_();   // orders c pushes (both CTAs) + x writeback
        } else {
            // last layer: write straight to global for the dense head
#pragma unroll
            for (int r = 0; r < 4; r++) {
                float4* dst = reinterpret_cast<float4*>(
                    g_x0 + (size_t)b * 32768 + (h * 256 + r0 + r) * 64 + cs0);
                dst[0] = make_float4(o[r][0], o[r][1], o[r][2], o[r][3]);
                dst[1] = make_float4(o[r][4], o[r][5], o[r][6], o[r][7]);
            }
        }
    }
}

// ----------------------------------------------------------------------------
// Dense layer 0 split-K: 128 CTAs, each owns a K-chunk of 256. f32x2 packed.
// (R12 configuration — the 256-CTA variant regressed the dense head.)
// ----------------------------------------------------------------------------
#define D0XS 257
__global__ __launch_bounds__(256, 1) void dense0_kernel(const float* __restrict__ W)
{
    extern __shared__ float sm[];
    float* Xs = sm;                 // 64 x 257 (padded)
    float* Ws = Xs + 64 * D0XS;     // 256 x 128
    const int tid = threadIdx.x;
    const int kc  = blockIdx.x;

    for (int idx = tid; idx < 64 * 256; idx += 256) {
        int bb = idx >> 8, k = idx & 255;
        Xs[bb * D0XS + k] = g_x0[(size_t)bb * 32768 + kc * 256 + k];
    }
    const float* wsrc = W + (size_t)kc * 256 * 128;
    for (int idx = tid; idx < 256 * 128 / 4; idx += 256)
        reinterpret_cast<float4*>(Ws)[idx] =
            reinterpret_cast<const float4*>(wsrc)[idx];
    __syncthreads();

    const int rg = tid >> 4;   // 0..15 -> rows rg*4..rg*4+3
    const int cg = tid & 15;   // 0..15 -> cols cg*8..cg*8+7
    ull acc[4][4];
#pragma unroll
    for (int r = 0; r < 4; r++)
#pragma unroll
        for (int c = 0; c < 4; c++) acc[r][c] = 0ull;

#pragma unroll 2
    for (int k = 0; k < 256; k++) {
        ulonglong2 w01 = *reinterpret_cast<const ulonglong2*>(&Ws[k * 128 + cg * 8]);
        ulonglong2 w23 = *reinterpret_cast<const ulonglong2*>(&Ws[k * 128 + cg * 8 + 4]);
#pragma unroll
        for (int r = 0; r < 4; r++) {
            float xv = Xs[(rg * 4 + r) * D0XS + k];
            ull xp = pk2(xv, xv);
            acc[r][0] = fma2_(xp, w01.x, acc[r][0]);
            acc[r][1] = fma2_(xp, w01.y, acc[r][1]);
            acc[r][2] = fma2_(xp, w23.x, acc[r][2]);
            acc[r][3] = fma2_(xp, w23.y, acc[r][3]);
        }
    }
    float* dst = g_part + (size_t)kc * 8192;
#pragma unroll
    for (int r = 0; r < 4; r++) {
        ulonglong2* d = reinterpret_cast<ulonglong2*>(&dst[(rg * 4 + r) * 128 + cg * 8]);
        d[0] = make_ulonglong2(acc[r][0], acc[r][1]);
        d[1] = make_ulonglong2(acc[r][2], acc[r][3]);
    }
}

// ----------------------------------------------------------------------------
// Finalize: reduce partials, BN+sigmoid, dense1, BN+sigmoid, W2, write (64,4)
// ----------------------------------------------------------------------------
__global__ __launch_bounds__(128, 1) void finalize_kernel(
    const float* __restrict__ db0, const float* __restrict__ dW1,
    const float* __restrict__ db1, const float* __restrict__ dbng,
    const float* __restrict__ dbnb, const float* __restrict__ W2,
    const float* __restrict__ b2, float* __restrict__ out)
{
    __shared__ float h0[128];
    __shared__ float h1[128];
    const int b = blockIdx.x;
    const int d = threadIdx.x;

    float a = db0[d];
#pragma unroll 4
    for (int kc = 0; kc < 128; kc++) a += g_part[(size_t)kc * 8192 + b * 128 + d];
    a = fmaf(dbng[d] * ISRC, a, dbnb[d]);
    h0[d] = 1.f / (1.f + __expf(-a));
    __syncthreads();

    float s = 0.f;
#pragma unroll 8
    for (int k = 0; k < 128; k++) s = fmaf(h0[k], dW1[k * 128 + d], s);
    s += db1[d];
    s = fmaf(dbng[128 + d] * ISRC, s, dbnb[128 + d]);
    h1[d] = 1.f / (1.f + __expf(-s));
    __syncthreads();

    if (d < 4) {
        float o = 0.f;
        if (d < 2) {
            o = b2[d];
            for (int k = 0; k < 128; k++) o = fmaf(h1[k], W2[k * 2 + d], o);
        }
        out[b * 4 + d] = o;
    }
}

// ----------------------------------------------------------------------------
extern "C" void kernel_launch(void* const* d_in, const int* in_sizes, int n_in,
                              void* d_out, int out_size)
{
    const float* xx   = (const float*)d_in[0];
    const float* emb1 = (const float*)d_in[1];
    const float* emb2 = (const float*)d_in[2];
    const float* emb3 = (const float*)d_in[3];
    const float* A0   = (const float*)d_in[4];
    const float* b0   = (const float*)d_in[5];
    const float* Ar   = (const float*)d_in[6];
    const float* br   = (const float*)d_in[7];
    const float* bng  = (const float*)d_in[8];
    const float* bnb  = (const float*)d_in[9];
    const float* dW0  = (const float*)d_in[10];
    const float* db0  = (const float*)d_in[11];
    const float* dW1  = (const float*)d_in[12];
    const float* db1  = (const float*)d_in[13];
    const float* dbng = (const float*)d_in[14];
    const float* dbnb = (const float*)d_in[15];
    const float* W2   = (const float*)d_in[16];
    const float* b2   = (const float*)d_in[17];
    float* out = (float*)d_out;

    // 5120 + 17408 + 16512 + 256 + 512 + 512 + 960 = 41280 floats
    const int G_SMEM  = 41280 * 4;
    const int D0_SMEM = (64 * D0XS + 256 * 128) * 4;

    cudaFuncSetAttribute(gnn_fused_kernel,
                         cudaFuncAttributeMaxDynamicSharedMemorySize, G_SMEM);
    cudaFuncSetAttribute(dense0_kernel,
                         cudaFuncAttributeMaxDynamicSharedMemorySize, D0_SMEM);

    dim3 grid(2, 64);
    gnn_fused_kernel<<<grid, 512, G_SMEM>>>(
        xx, emb1, emb2, emb3, A0, b0, Ar, br, bng, bnb);
    dense0_kernel<<<128, 256, D0_SMEM>>>(dW0);
    finalize_kernel<<<64, 128>>>(db0, dW1, db1, dbng, dbnb, W2, b2, out);
}